// round 14
// baseline (speedup 1.0000x reference)
#include <cuda_runtime.h>
#include <cstdint>

// Problem shape (fixed by the dataset)
#define BB 4
#define LL 2048
#define CC 1024

// Tiling: one warp per block, warp = G groups x CT channels
#define CT 4             // channels per block (lanes c = lane & 3)
#define G  8             // chunk groups (lanes g = lane >> 2)
#define EPT 4            // L elements per thread per piece
#define LP (G * EPT)     // 32 L elements per piece
#define THREADS (CT * G) // 32 (one warp)
#define PIECES (LL / LP) // 64

#define FULLMASK 0xffffffffu

typedef unsigned long long u64;   // one complex number: lo=re, hi=im

__device__ __forceinline__ u64 pk2(float lo, float hi) {
    u64 r; asm("mov.b64 %0, {%1,%2};" : "=l"(r) : "f"(lo), "f"(hi)); return r;
}
__device__ __forceinline__ void unpk2(u64 x, float& lo, float& hi) {
    asm("mov.b64 {%0,%1}, %2;" : "=f"(lo), "=f"(hi) : "l"(x));
}
// packed (a.lo*b.lo+c.lo, a.hi*b.hi+c.hi)
__device__ __forceinline__ u64 fma2(u64 a, u64 b, u64 c) {
    u64 r; asm("fma.rn.f32x2 %0, %1, %2, %3;" : "=l"(r) : "l"(a), "l"(b), "l"(c)); return r;
}

// Complex p prepped for multiplication: s=(re,re), n=(-im,im)
struct CPrep { u64 s, n; };
__device__ __forceinline__ CPrep prep(u64 p) {
    float re, im; unpk2(p, re, im);
    CPrep o; o.s = pk2(re, re); o.n = pk2(-im, im); return o;
}
__device__ __forceinline__ u64 swp(u64 q) {   // (im, re)
    float re, im; unpk2(q, re, im); return pk2(im, re);
}
// complex r = p*q + c :  (pr*qr - pi*qi, pr*qi + pi*qr) + c
__device__ __forceinline__ u64 cfma(CPrep p, u64 q, u64 qs, u64 c) {
    return fma2(p.s, q, fma2(p.n, qs, c));
}

// 2x2 complex matrix = u64[4], row-major e[i*2+j]
struct MPrep { CPrep e[4]; };
__device__ __forceinline__ MPrep mprep(const u64* P) {
    MPrep m;
#pragma unroll
    for (int k = 0; k < 4; k++) m.e[k] = prep(P[k]);
    return m;
}
__device__ __forceinline__ void mswp(const u64* Q, u64* qs) {
#pragma unroll
    for (int k = 0; k < 4; k++) qs[k] = swp(Q[k]);
}
// R = P @ Q (+ C); qs = swapped Q entries
__device__ __forceinline__ void mmul(const MPrep& P, const u64* Q, const u64* qs,
                                     const u64* C, u64* R) {
#pragma unroll
    for (int i = 0; i < 2; i++)
#pragma unroll
        for (int j = 0; j < 2; j++) {
            u64 acc = C ? C[i * 2 + j] : 0ull;
            acc = cfma(P.e[i * 2 + 1], Q[2 + j], qs[2 + j], acc);
            acc = cfma(P.e[i * 2 + 0], Q[j],     qs[j],     acc);
            R[i * 2 + j] = acc;
        }
}
__device__ __forceinline__ void mcp(const u64* s, u64* d) {
#pragma unroll
    for (int k = 0; k < 4; k++) d[k] = s[k];
}
__device__ __forceinline__ void mshfl_up(const u64* s, u64* d, int delta) {
#pragma unroll
    for (int k = 0; k < 4; k++) d[k] = __shfl_up_sync(FULLMASK, s[k], delta);
}

__device__ __forceinline__ void ld_mat_cs(const char* p, u64* m) {
    asm("ld.global.cs.v2.u64 {%0,%1}, [%2];"    : "=l"(m[0]), "=l"(m[1]) : "l"(p));
    asm("ld.global.cs.v2.u64 {%0,%1}, [%2+16];" : "=l"(m[2]), "=l"(m[3]) : "l"(p));
}
__device__ __forceinline__ void st_mat_cs(char* p, const u64* m) {
    asm("st.global.cs.v2.u64 [%0], {%1,%2};"    :: "l"(p), "l"(m[0]), "l"(m[1]) : "memory");
    asm("st.global.cs.v2.u64 [%0+16], {%1,%2};" :: "l"(p), "l"(m[2]), "l"(m[3]) : "memory");
}

struct Ctx {
    const char* A;
    const char* X;
    char* Y;
    long long base;  // byte offset of (piece 0, this thread's first row, channel)
    int g;
};

#define ROW_BYTES ((long long)CC * 32)   // one L-row of all channels, 32 B per matrix

// Load piece p's EPT matrices (A and X) into registers (streaming).
__device__ __forceinline__ void load_piece(const Ctx& ctx, int p,
                                           u64 (&Am)[EPT][4], u64 (&Xm)[EPT][4]) {
#pragma unroll
    for (int i = 0; i < EPT; i++) {
        const long long off = ctx.base + (long long)(p * LP + i) * ROW_BYTES;
        ld_mat_cs(ctx.A + off, Am[i]);
        ld_mat_cs(ctx.X + off, Xm[i]);
    }
}

// Scan one piece (data in registers), update carry, write output.
// On exit Am[i]/Xm[i] are destroyed (hold per-row inclusive prefixes).
__device__ __forceinline__ void compute_piece(const Ctx& ctx, int p,
                                              u64 (&Am)[EPT][4], u64 (&Xm)[EPT][4],
                                              u64 (&carry)[4]) {
    const int g = ctx.g;
    const int c = threadIdx.x & (CT - 1);

    // ---- in-place per-row inclusive prefixes within this lane ----
    // After: Am[i] = prod A_{0..i}, Xm[i] = inclusive scan value (A-part applied)
#pragma unroll
    for (int i = 1; i < EPT; i++) {
        MPrep P = mprep(Am[i]);            // A_i (original)
        u64 qsA[4], qsX[4], tA[4], tX[4];
        mswp(Am[i - 1], qsA);
        mswp(Xm[i - 1], qsX);
        mmul(P, Am[i - 1], qsA, nullptr, tA);      // A_i @ IA_{i-1}
        mmul(P, Xm[i - 1], qsX, Xm[i], tX);        // A_i @ IX_{i-1} + X_i
        mcp(tA, Am[i]);
        mcp(tX, Xm[i]);
    }

    // ---- inclusive Kogge-Stone scan over the G groups (shuffle-based) ----
    u64 IA[4], IX[4];
    mcp(Am[EPT - 1], IA);
    mcp(Xm[EPT - 1], IX);
#pragma unroll
    for (int d = 1; d < G; d <<= 1) {
        u64 tA[4], tX[4];
        mshfl_up(IA, tA, d * CT);
        mshfl_up(IX, tX, d * CT);
        if (g >= d) {
            MPrep P = mprep(IA);           // later aggregate
            u64 qa[4], qx[4], nA[4], nX[4];
            mswp(tA, qa);
            mswp(tX, qx);
            mmul(P, tA, qa, nullptr, nA);  // A_later @ A_earlier
            mmul(P, tX, qx, IX, nX);       // A_later @ X_earlier + X_later
            mcp(nA, IA);
            mcp(nX, IX);
        }
    }

    // ---- exclusive prefix (from lane g-1) and full-piece aggregate (lane G-1) ----
    u64 EA[4], EX[4], FA[4], FX[4];
    mshfl_up(IA, EA, CT);
    mshfl_up(IX, EX, CT);
#pragma unroll
    for (int k = 0; k < 4; k++) {
        FA[k] = __shfl_sync(FULLMASK, IA[k], (G - 1) * CT + c);
        FX[k] = __shfl_sync(FULLMASK, IX[k], (G - 1) * CT + c);
    }

    // start value for this group's outputs (uses OLD carry)
    u64 cs[4];
    mswp(carry, cs);
    u64 Yp[4];
    if (g == 0) {
        mcp(carry, Yp);
    } else {
        MPrep P = mprep(EA);
        mmul(P, carry, cs, EX, Yp);        // A_{0..g-1} @ carry + X_{0..g-1}
    }
    {   // next piece's carry (uses OLD carry)
        MPrep P = mprep(FA);
        u64 nc[4];
        mmul(P, carry, cs, FX, nc);        // A_{0..G-1} @ carry + X_{0..G-1}
        mcp(nc, carry);
    }

    // ---- epilogue: 4 INDEPENDENT outputs  Y_i = IA_i @ Yp + IX_i ----
    u64 ys[4];
    mswp(Yp, ys);
#pragma unroll
    for (int i = 0; i < EPT; i++) {
        MPrep P = mprep(Am[i]);
        u64 Yi[4];
        mmul(P, Yp, ys, Xm[i], Yi);
        st_mat_cs(ctx.Y + ctx.base + (long long)(p * LP + i) * ROW_BYTES, Yi);
    }
}

__global__ void __launch_bounds__(THREADS, 1)   // allow ptxas up to 255 regs
pscan_kernel(const float* __restrict__ Ag, const float* __restrict__ Xg,
             float* __restrict__ Yg) {
    const int lane = threadIdx.x;
    const int c = lane & (CT - 1);
    const int g = lane >> 2;            // log2(CT) = 2
    const int b = blockIdx.y;
    const int c0 = blockIdx.x * CT;

    Ctx ctx;
    ctx.A = (const char*)Ag;
    ctx.X = (const char*)Xg;
    ctx.Y = (char*)Yg;
    ctx.g = g;
    // byte offset of this lane's (first-row-of-its-chunk, channel) at piece 0
    ctx.base = ((long long)(b * LL + g * EPT) * CC + (c0 + c)) * 32;

    u64 carry[4];
#pragma unroll
    for (int k = 0; k < 4; k++) carry[k] = 0ull;

    u64 A0[EPT][4], X0[EPT][4], A1[EPT][4], X1[EPT][4];

    // prologue: piece 0 into buf0
    load_piece(ctx, 0, A0, X0);

#pragma unroll 1
    for (int p = 0; p < PIECES; p += 2) {
        // prefetch p+1 into buf1 while computing p from buf0
        load_piece(ctx, p + 1, A1, X1);
        compute_piece(ctx, p, A0, X0, carry);
        // prefetch p+2 into buf0 while computing p+1 from buf1
        if (p + 2 < PIECES) load_piece(ctx, p + 2, A0, X0);
        compute_piece(ctx, p + 1, A1, X1, carry);
    }
}

extern "C" void kernel_launch(void* const* d_in, const int* in_sizes, int n_in,
                              void* d_out, int out_size) {
    const float* A = (const float*)d_in[0];
    const float* X = (const float*)d_in[1];
    float* Y = (float*)d_out;

    dim3 grid(CC / CT, BB);   // 256 x 4 = 1024 one-warp CTAs
    pscan_kernel<<<grid, THREADS>>>(A, X, Y);
}